// round 14
// baseline (speedup 1.0000x reference)
#include <cuda_runtime.h>
#include <cuda_bf16.h>
#include <cstdint>
#include <cstddef>

#define T_DIM  32
#define K2     512
#define KD     262144
#define THRESH 0.2f

#define KSPLIT 148                         // grid 4*148 = 592 = 148 SMs * 4
#define KSLAB  16                          // fp32 k per pipeline stage
#define NSLAB_TOT (KD / KSLAB)             // 16384
#define SBASE (NSLAB_TOT / KSPLIT)         // 110
#define SREM  (NSLAB_TOT - SBASE * KSPLIT) // 104

#define STAGES   3
#define A_STRIDE 96                        // 64B data + 32B pad: conflict-free lds64
#define A_BYTES  (128 * A_STRIDE)          // 12288
#define BH_OFF   A_BYTES
#define BB_STRIDE 48                       // bf16 rows: 32B data + 16B pad
#define BL_OFF   (BH_OFF + 32 * BB_STRIDE) // 13824
#define STAGE_BYTES (BL_OFF + 32 * BB_STRIDE)   // 15360
#define SMEM_TOTAL  (STAGES * STAGE_BYTES)      // 46080 (x4 CTAs = 184KB)

__device__ float g_partial[(size_t)KSPLIT * T_DIM * K2];
__device__ float g_dot[T_DIM * K2];

// ---------------- helpers ----------------
__device__ __forceinline__ uint32_t smem_u32(const void* p) {
    uint32_t a;
    asm("{ .reg .u64 t; cvta.to.shared.u64 t, %1; cvt.u32.u64 %0, t; }"
        : "=r"(a) : "l"(p));
    return a;
}
__device__ __forceinline__ void cp16(uint32_t dst, const void* src) {
    asm volatile("cp.async.cg.shared.global [%0], [%1], 16;"
                 :: "r"(dst), "l"(src) : "memory");
}
__device__ __forceinline__ float2 lds64(uint32_t a) {
    float2 v;
    asm volatile("ld.shared.v2.f32 {%0,%1}, [%2];"
                 : "=f"(v.x), "=f"(v.y) : "r"(a));
    return v;
}
__device__ __forceinline__ void sts32(uint32_t a, uint32_t x) {
    asm volatile("st.shared.b32 [%0], %1;" :: "r"(a), "r"(x) : "memory");
}
__device__ __forceinline__ void ldsm_x4(uint32_t* r, uint32_t addr) {
    asm volatile("ldmatrix.sync.aligned.m8n8.x4.shared.b16 {%0,%1,%2,%3}, [%4];"
                 : "=r"(r[0]), "=r"(r[1]), "=r"(r[2]), "=r"(r[3]) : "r"(addr));
}
__device__ __forceinline__ void mma_bf16(float* c, const uint32_t* a, const uint32_t* b) {
    asm volatile("mma.sync.aligned.m16n8k16.row.col.f32.bf16.bf16.f32 "
                 "{%0,%1,%2,%3}, {%4,%5,%6,%7}, {%8,%9}, {%0,%1,%2,%3};"
                 : "+f"(c[0]), "+f"(c[1]), "+f"(c[2]), "+f"(c[3])
                 : "r"(a[0]), "r"(a[1]), "r"(a[2]), "r"(a[3]),
                   "r"(b[0]), "r"(b[1]));
}
__device__ __forceinline__ void cvt2(float a, float b, uint32_t& h, uint32_t& l) {
    __nv_bfloat162 hb = __floats2bfloat162_rn(a, b);
    float2 hf = __bfloat1622float2(hb);
    __nv_bfloat162 lb = __floats2bfloat162_rn(a - hf.x, b - hf.y);
    h = *reinterpret_cast<uint32_t*>(&hb);
    l = *reinterpret_cast<uint32_t*>(&lb);
}

// ---------------------------------------------------------------------------
// cp.async-pipelined HMMA GEMM, 3-stage ring, 4 CTAs/SM, KSLAB=16.
// A (W) staged fp32 via cp.async (conflict-free 96B rows);
// B (rec) LDG->reg->block convert->bf16 smem (48B rows); ldmatrix.x4 B.
// bf16 3-product (hh+hl+lh), fp32 accum. warp = 16 o x 32 t.
// ---------------------------------------------------------------------------
__global__ void __launch_bounds__(256, 4)
gemm_pipe(const float* __restrict__ rec, const float* __restrict__ wgt)
{
    extern __shared__ __align__(128) char smem[];
    const uint32_t sbase = smem_u32(smem);

    const int tid = threadIdx.x;
    const int wid = tid >> 5;
    const int lid = tid & 31;
    const int g   = lid >> 2;
    const int tig = lid & 3;
    const int ot  = blockIdx.x;        // 0..3
    const int sp  = blockIdx.y;        // 0..147
    const int obase = ot * 128;

    const int s_begin = sp * SBASE + (sp < SREM ? sp : SREM);
    const int s_count = SBASE + (sp < SREM ? 1 : 0);

    // ---- A staging: thread covers rows (tid>>2)+{0,64}, 16B chunk tid&3 ----
    const float* asrc0 = wgt + (size_t)(obase + (tid >> 2)) * KD
                         + (size_t)s_begin * KSLAB + (tid & 3) * 4;
    const uint32_t adst0 = sbase + (uint32_t)((tid >> 2) * A_STRIDE + (tid & 3) * 16);

#define ISSUE(S)                                                              \
    {   const uint32_t so = (uint32_t)((S) % 3) * STAGE_BYTES;                 \
        const size_t ko = (size_t)(S) * KSLAB;                                 \
        cp16(adst0 + so,                 asrc0 + ko);                          \
        cp16(adst0 + so + 64 * A_STRIDE, asrc0 + ko + (size_t)64 * KD); }

    // ---- B map: thread covers row tid>>3, 8B chunk tid&7 (2 floats) ----
    const int brow = tid >> 3, bchk = tid & 7;
    const float* bsrc = rec + (size_t)brow * KD
                        + (size_t)s_begin * KSLAB + bchk * 2;
    const uint32_t cvt_h = sbase + (uint32_t)(BH_OFF + brow * BB_STRIDE + bchk * 4);
    const uint32_t cvt_l = sbase + (uint32_t)(BL_OFF + brow * BB_STRIDE + bchk * 4);

    // ---- compute lane addresses ----
    const uint32_t a0b = sbase + (uint32_t)((wid * 16 + g) * A_STRIDE + tig * 8);
    const uint32_t a1b = a0b + 8 * A_STRIDE;
    // ldsm x4 B: lanes 0-15 -> n-tile np*2, lanes 16-31 -> np*2+1
    const uint32_t bb  = sbase + (uint32_t)(BH_OFF + (lid & 7) * BB_STRIDE
                          + ((lid >> 3) & 1) * 16
                          + (lid >> 4) * (8 * BB_STRIDE));

    float acc[4][4];
#pragma unroll
    for (int nt = 0; nt < 4; nt++)
#pragma unroll
        for (int i = 0; i < 4; i++) acc[nt][i] = 0.0f;

    // prologue
    ISSUE(0) asm volatile("cp.async.commit_group;" ::: "memory");
    ISSUE(1) asm volatile("cp.async.commit_group;" ::: "memory");
    float2 breg = *reinterpret_cast<const float2*>(bsrc);

    for (int s = 0; s < s_count; s++) {
        asm volatile("cp.async.wait_group 1;" ::: "memory");

        const uint32_t so = (uint32_t)(s % 3) * STAGE_BYTES;

        // block-shared B convert from registers into bf16 hi/lo tiles
        {
            uint32_t h0, l0;
            cvt2(breg.x, breg.y, h0, l0);
            sts32(cvt_h + so, h0);
            sts32(cvt_l + so, l0);
        }
        __syncthreads();   // publishes A(s)+B(s); frees ring slot (s-1)%3

        if (s + 2 < s_count) ISSUE(s + 2)
        asm volatile("cp.async.commit_group;" ::: "memory");
        if (s + 1 < s_count)
            breg = *reinterpret_cast<const float2*>(bsrc + (size_t)(s + 1) * KSLAB);

        // single k16 step
        const float2 f0 = lds64(a0b + so);
        const float2 f1 = lds64(a1b + so);
        const float2 f2 = lds64(a0b + so + 32);
        const float2 f3 = lds64(a1b + so + 32);
        uint32_t Ah[4], Al[4];
        cvt2(f0.x, f0.y, Ah[0], Al[0]);
        cvt2(f1.x, f1.y, Ah[1], Al[1]);
        cvt2(f2.x, f2.y, Ah[2], Al[2]);
        cvt2(f3.x, f3.y, Ah[3], Al[3]);
        const uint32_t bo = bb + so;
#pragma unroll
        for (int np = 0; np < 2; np++) {
            uint32_t Bh[4], Bl[4];              // two n-tiles per ldsm.x4
            ldsm_x4(Bh, bo + np * (16 * BB_STRIDE));
            ldsm_x4(Bl, bo + np * (16 * BB_STRIDE) + (BL_OFF - BH_OFF));
            mma_bf16(acc[np * 2 + 0], Ah, Bh + 0);
            mma_bf16(acc[np * 2 + 0], Ah, Bl + 0);
            mma_bf16(acc[np * 2 + 0], Al, Bh + 0);
            mma_bf16(acc[np * 2 + 1], Ah, Bh + 2);
            mma_bf16(acc[np * 2 + 1], Ah, Bl + 2);
            mma_bf16(acc[np * 2 + 1], Al, Bh + 2);
        }
    }

    // epilogue
    const int orow = obase + wid * 16 + g;
#pragma unroll
    for (int nt = 0; nt < 4; nt++)
#pragma unroll
        for (int c = 0; c < 4; c++) {
            const int o = orow + ((c >> 1) ? 8 : 0);
            const int t = nt * 8 + 2 * tig + (c & 1);
            g_partial[((size_t)sp * T_DIM + t) * K2 + o] = acc[nt][c];
        }
}

// ---------------------------------------------------------------------------
// deterministic split-K reduction
// ---------------------------------------------------------------------------
__global__ void __launch_bounds__(512) reduce_kernel()
{
    const int t = blockIdx.x;
    const int o = threadIdx.x;
    const size_t stride = (size_t)T_DIM * K2;
    const size_t idx = (size_t)t * K2 + o;
    float s = 0.0f;
#pragma unroll
    for (int sp = 0; sp < KSPLIT; sp++)
        s += g_partial[(size_t)sp * stride + idx];
    g_dot[t * K2 + o] = s;
}

// ---------------------------------------------------------------------------
// post: threshold -> first-spike -> totals -> 8-round k-WTA (shuffle argmax)
// ---------------------------------------------------------------------------
__global__ void __launch_bounds__(512) post_kernel(float* __restrict__ outp)
{
    const int o    = threadIdx.x;
    const int lane = o & 31;
    const int w    = o >> 5;

    unsigned mask = 0;
    int cnt = 0;
#pragma unroll
    for (int t = 0; t < T_DIM; t++) {
        const float v = g_dot[t * K2 + o];
        if (v >= THRESH) { cnt++; mask |= (1u << t); }
    }
    int first = T_DIM - cnt;
    if (first > T_DIM - 1) first = T_DIM - 1;
    const float fv    = g_dot[first * K2 + o];
    const float value = (fv < THRESH) ? 0.0f : fv;
    const float cand  = (cnt > 0) ? value : 0.0f;

    __shared__ float wmaxf[16];
    __shared__ unsigned long long wmax[16];
    __shared__ int s_win;

    float m = cand;
#pragma unroll
    for (int off = 16; off; off >>= 1)
        m = fmaxf(m, __shfl_xor_sync(0xffffffffu, m, off));
    if (lane == 0) wmaxf[w] = m;
    __syncthreads();
    if (o == 0) {
        float mm = wmaxf[0];
#pragma unroll
        for (int i = 1; i < 16; i++) mm = fmaxf(mm, wmaxf[i]);
        wmaxf[0] = mm;
    }
    __syncthreads();
    const float voff = wmaxf[0] * (float)T_DIM;

    float tot = (cnt > 0) ? (float)cnt * (value + voff) : 0.0f;
    bool sel = false;

    for (int r = 0; r < 8; r++) {
        unsigned long long pk =
            ((unsigned long long)__float_as_uint(tot) << 32)
            | (unsigned)(K2 - 1 - o);
#pragma unroll
        for (int off = 16; off; off >>= 1) {
            unsigned long long other = __shfl_xor_sync(0xffffffffu, pk, off);
            if (other > pk) pk = other;
        }
        if (lane == 0) wmax[w] = pk;
        __syncthreads();
        if (o == 0) {
            unsigned long long best = wmax[0];
#pragma unroll
            for (int i = 1; i < 16; i++) if (wmax[i] > best) best = wmax[i];
            s_win = (K2 - 1) - (int)(unsigned)(best & 0xffffffffULL);
        }
        __syncthreads();
        if (o == s_win) {
            if (tot != 0.0f) sel = true;
            tot = 0.0f;
        }
        __syncthreads();
    }

#pragma unroll
    for (int t = 0; t < T_DIM; t++) {
        outp[t * K2 + o] = (sel && ((mask >> t) & 1u)) ? 1.0f : 0.0f;
    }
}

// ---------------------------------------------------------------------------
extern "C" void kernel_launch(void* const* d_in, const int* in_sizes, int n_in,
                              void* d_out, int out_size)
{
    const float* rec = (const float*)d_in[0];   // (32,1,64,4096)
    const float* wgt = (const float*)d_in[1];   // (512,1,64,4096)
    if (n_in >= 2 && in_sizes[0] > in_sizes[1]) {
        const float* tmp = rec; rec = wgt; wgt = tmp;
    }
    float* outp = (float*)d_out;

    cudaFuncSetAttribute(gemm_pipe, cudaFuncAttributeMaxDynamicSharedMemorySize,
                         SMEM_TOTAL);

    gemm_pipe<<<dim3(4, KSPLIT), 256, SMEM_TOTAL>>>(rec, wgt);
    reduce_kernel<<<T_DIM, K2>>>();
    post_kernel<<<1, K2>>>(outp);
}

// round 15
// speedup vs baseline: 1.3871x; 1.3871x over previous
#include <cuda_runtime.h>
#include <cuda_bf16.h>
#include <cstdint>
#include <cstddef>

#define T_DIM  32
#define K2     512
#define KD     262144
#define THRESH 0.2f

#define KSPLIT 148                         // grid 4*148 = 592 = 148 SMs * 4
#define KSLAB  32                          // fp32 k per pipeline stage
#define NSLAB_TOT (KD / KSLAB)             // 8192
#define SBASE (NSLAB_TOT / KSPLIT)         // 55
#define SREM  (NSLAB_TOT - SBASE * KSPLIT) // 52

#define STAGES   2
#define A_STRIDE 160                       // 128B data + 32B pad: phase-CF lds64
#define A_BYTES  (128 * A_STRIDE)          // 20480
#define BH_OFF   A_BYTES
#define BB_STRIDE 80                       // bf16 rows: 64B data + 16B pad
#define BL_OFF   (BH_OFF + 32 * BB_STRIDE)
#define STAGE_BYTES (BL_OFF + 32 * BB_STRIDE)   // 25600
#define SMEM_TOTAL  (STAGES * STAGE_BYTES)      // 51200 (x4 CTAs = 204.8KB)

__device__ float g_partial[(size_t)KSPLIT * T_DIM * K2];
__device__ float g_dot[T_DIM * K2];

// ---------------- helpers ----------------
__device__ __forceinline__ uint32_t smem_u32(const void* p) {
    uint32_t a;
    asm("{ .reg .u64 t; cvta.to.shared.u64 t, %1; cvt.u32.u64 %0, t; }"
        : "=r"(a) : "l"(p));
    return a;
}
__device__ __forceinline__ void cp16(uint32_t dst, const void* src) {
    asm volatile("cp.async.cg.shared.global [%0], [%1], 16;"
                 :: "r"(dst), "l"(src) : "memory");
}
__device__ __forceinline__ float2 lds64(uint32_t a) {
    float2 v;
    asm volatile("ld.shared.v2.f32 {%0,%1}, [%2];"
                 : "=f"(v.x), "=f"(v.y) : "r"(a));
    return v;
}
__device__ __forceinline__ void sts64(uint32_t a, uint32_t x, uint32_t y) {
    asm volatile("st.shared.v2.b32 [%0], {%1,%2};" :: "r"(a), "r"(x), "r"(y)
                 : "memory");
}
__device__ __forceinline__ void ldsm_x4(uint32_t* r, uint32_t addr) {
    asm volatile("ldmatrix.sync.aligned.m8n8.x4.shared.b16 {%0,%1,%2,%3}, [%4];"
                 : "=r"(r[0]), "=r"(r[1]), "=r"(r[2]), "=r"(r[3]) : "r"(addr));
}
__device__ __forceinline__ void mma_bf16(float* c, const uint32_t* a, const uint32_t* b) {
    asm volatile("mma.sync.aligned.m16n8k16.row.col.f32.bf16.bf16.f32 "
                 "{%0,%1,%2,%3}, {%4,%5,%6,%7}, {%8,%9}, {%0,%1,%2,%3};"
                 : "+f"(c[0]), "+f"(c[1]), "+f"(c[2]), "+f"(c[3])
                 : "r"(a[0]), "r"(a[1]), "r"(a[2]), "r"(a[3]),
                   "r"(b[0]), "r"(b[1]));
}
__device__ __forceinline__ void cvt2(float a, float b, uint32_t& h, uint32_t& l) {
    __nv_bfloat162 hb = __floats2bfloat162_rn(a, b);
    float2 hf = __bfloat1622float2(hb);
    __nv_bfloat162 lb = __floats2bfloat162_rn(a - hf.x, b - hf.y);
    h = *reinterpret_cast<uint32_t*>(&hb);
    l = *reinterpret_cast<uint32_t*>(&lb);
}

// ---------------------------------------------------------------------------
// cp.async-pipelined HMMA GEMM, 2-stage ring, 4 CTAs/SM, 1 barrier/slab.
// A (W) staged fp32 via cp.async (phase-conflict-free 160B rows);
// B (rec) LDG->reg->block convert->bf16 smem; ldmatrix.x4 B fragments.
// bf16 3-product (hh+hl+lh), fp32 accum. warp = 16 o x 32 t.
// ---------------------------------------------------------------------------
__global__ void __launch_bounds__(256, 4)
gemm_pipe(const float* __restrict__ rec, const float* __restrict__ wgt)
{
    extern __shared__ __align__(128) char smem[];
    const uint32_t sbase = smem_u32(smem);

    const int tid = threadIdx.x;
    const int wid = tid >> 5;
    const int lid = tid & 31;
    const int g   = lid >> 2;
    const int tig = lid & 3;
    const int ot  = blockIdx.x;        // 0..3
    const int sp  = blockIdx.y;        // 0..147
    const int obase = ot * 128;

    const int s_begin = sp * SBASE + (sp < SREM ? sp : SREM);
    const int s_count = SBASE + (sp < SREM ? 1 : 0);

    // ---- A staging map: thread covers rows (tid>>3)+32j, chunk tid&7 ----
    const float* asrc0 = wgt + (size_t)(obase + (tid >> 3)) * KD
                         + (size_t)s_begin * KSLAB + (tid & 7) * 4;
    const uint32_t adst0 = sbase + (uint32_t)((tid >> 3) * A_STRIDE + (tid & 7) * 16);

#define ISSUE(S)                                                              \
    {   const uint32_t so = (uint32_t)((S) & 1) * STAGE_BYTES;                 \
        const size_t ko = (size_t)(S) * KSLAB;                                 \
        cp16(adst0 + so,                    asrc0 + ko);                       \
        cp16(adst0 + so + 32 * A_STRIDE,    asrc0 + ko + (size_t)32 * KD);     \
        cp16(adst0 + so + 64 * A_STRIDE,    asrc0 + ko + (size_t)64 * KD);     \
        cp16(adst0 + so + 96 * A_STRIDE,    asrc0 + ko + (size_t)96 * KD); }

    // ---- B map: thread covers row tid>>3, chunk tid&7 (4 floats) ----
    const int brow = tid >> 3, bchk = tid & 7;
    const float* bsrc = rec + (size_t)brow * KD
                        + (size_t)s_begin * KSLAB + bchk * 4;
    const uint32_t cvt_h = sbase + (uint32_t)(BH_OFF + brow * BB_STRIDE + bchk * 8);
    const uint32_t cvt_l = sbase + (uint32_t)(BL_OFF + brow * BB_STRIDE + bchk * 8);

    // ---- compute lane addresses ----
    const uint32_t a0b = sbase + (uint32_t)((wid * 16 + g) * A_STRIDE + tig * 8);
    const uint32_t a1b = a0b + 8 * A_STRIDE;
    // ldsm x4 B address: lanes 0-15 -> n-tile nt, lanes 16-31 -> nt+1
    const uint32_t bb  = sbase + (uint32_t)(BH_OFF + (lid & 7) * BB_STRIDE
                          + ((lid >> 3) & 1) * 16
                          + (lid >> 4) * (8 * BB_STRIDE));

    float acc[4][4];
#pragma unroll
    for (int nt = 0; nt < 4; nt++)
#pragma unroll
        for (int i = 0; i < 4; i++) acc[nt][i] = 0.0f;

    // prologue
    ISSUE(0) asm volatile("cp.async.commit_group;" ::: "memory");
    float4 breg = *reinterpret_cast<const float4*>(bsrc);

#pragma unroll 2
    for (int s = 0; s < s_count; s++) {
        asm volatile("cp.async.wait_group 0;" ::: "memory");

        // prefetch next slab's B bytes immediately (no hazard: gmem->reg)
        float4 bnext;
        if (s + 1 < s_count)
            bnext = *reinterpret_cast<const float4*>(bsrc + (size_t)(s + 1) * KSLAB);

        const uint32_t so = (uint32_t)(s & 1) * STAGE_BYTES;

        // block-shared B convert from registers into bf16 hi/lo tiles
        {
            uint32_t h0, l0, h1, l1;
            cvt2(breg.x, breg.y, h0, l0);
            cvt2(breg.z, breg.w, h1, l1);
            sts64(cvt_h + so, h0, h1);
            sts64(cvt_l + so, l0, l1);
        }
        __syncthreads();   // publishes A(s) + converted B(s); frees slot s^1

        if (s + 1 < s_count) {
            ISSUE(s + 1)
            breg = bnext;
        }
        asm volatile("cp.async.commit_group;" ::: "memory");

#pragma unroll
        for (int ks = 0; ks < 2; ks++) {
            const uint32_t ao = so + ks * 64;
            const float2 f0 = lds64(a0b + ao);
            const float2 f1 = lds64(a1b + ao);
            const float2 f2 = lds64(a0b + ao + 32);
            const float2 f3 = lds64(a1b + ao + 32);
            uint32_t Ah[4], Al[4];
            cvt2(f0.x, f0.y, Ah[0], Al[0]);
            cvt2(f1.x, f1.y, Ah[1], Al[1]);
            cvt2(f2.x, f2.y, Ah[2], Al[2]);
            cvt2(f3.x, f3.y, Ah[3], Al[3]);
            const uint32_t bo = bb + so + ks * 32;
#pragma unroll
            for (int np = 0; np < 2; np++) {
                uint32_t Bh[4], Bl[4];          // two n-tiles per ldsm.x4
                ldsm_x4(Bh, bo + np * (16 * BB_STRIDE));
                ldsm_x4(Bl, bo + np * (16 * BB_STRIDE) + (BL_OFF - BH_OFF));
                mma_bf16(acc[np * 2 + 0], Ah, Bh + 0);
                mma_bf16(acc[np * 2 + 0], Ah, Bl + 0);
                mma_bf16(acc[np * 2 + 0], Al, Bh + 0);
                mma_bf16(acc[np * 2 + 1], Ah, Bh + 2);
                mma_bf16(acc[np * 2 + 1], Ah, Bl + 2);
                mma_bf16(acc[np * 2 + 1], Al, Bh + 2);
            }
        }
    }

    // epilogue
    const int orow = obase + wid * 16 + g;
#pragma unroll
    for (int nt = 0; nt < 4; nt++)
#pragma unroll
        for (int c = 0; c < 4; c++) {
            const int o = orow + ((c >> 1) ? 8 : 0);
            const int t = nt * 8 + 2 * tig + (c & 1);
            g_partial[((size_t)sp * T_DIM + t) * K2 + o] = acc[nt][c];
        }
}

// ---------------------------------------------------------------------------
// deterministic split-K reduction, 128 blocks (t x 4 o-chunks)
// ---------------------------------------------------------------------------
__global__ void __launch_bounds__(128) reduce_kernel()
{
    const int t = blockIdx.x;                      // 0..31
    const int o = blockIdx.y * 128 + threadIdx.x;  // 0..511
    const size_t stride = (size_t)T_DIM * K2;
    const size_t idx = (size_t)t * K2 + o;
    float s = 0.0f;
#pragma unroll
    for (int sp = 0; sp < KSPLIT; sp++)
        s += g_partial[(size_t)sp * stride + idx];
    g_dot[t * K2 + o] = s;
}

// ---------------------------------------------------------------------------
// post: threshold -> first-spike -> totals -> 8-round k-WTA (shuffle argmax)
// ---------------------------------------------------------------------------
__global__ void __launch_bounds__(512) post_kernel(float* __restrict__ outp)
{
    const int o    = threadIdx.x;
    const int lane = o & 31;
    const int w    = o >> 5;

    unsigned mask = 0;
    int cnt = 0;
#pragma unroll
    for (int t = 0; t < T_DIM; t++) {
        const float v = g_dot[t * K2 + o];
        if (v >= THRESH) { cnt++; mask |= (1u << t); }
    }
    int first = T_DIM - cnt;
    if (first > T_DIM - 1) first = T_DIM - 1;
    const float fv    = g_dot[first * K2 + o];
    const float value = (fv < THRESH) ? 0.0f : fv;
    const float cand  = (cnt > 0) ? value : 0.0f;

    __shared__ float wmaxf[16];
    __shared__ unsigned long long wmax[16];
    __shared__ int s_win;

    float m = cand;
#pragma unroll
    for (int off = 16; off; off >>= 1)
        m = fmaxf(m, __shfl_xor_sync(0xffffffffu, m, off));
    if (lane == 0) wmaxf[w] = m;
    __syncthreads();
    if (o == 0) {
        float mm = wmaxf[0];
#pragma unroll
        for (int i = 1; i < 16; i++) mm = fmaxf(mm, wmaxf[i]);
        wmaxf[0] = mm;
    }
    __syncthreads();
    const float voff = wmaxf[0] * (float)T_DIM;

    float tot = (cnt > 0) ? (float)cnt * (value + voff) : 0.0f;
    bool sel = false;

    for (int r = 0; r < 8; r++) {
        unsigned long long pk =
            ((unsigned long long)__float_as_uint(tot) << 32)
            | (unsigned)(K2 - 1 - o);
#pragma unroll
        for (int off = 16; off; off >>= 1) {
            unsigned long long other = __shfl_xor_sync(0xffffffffu, pk, off);
            if (other > pk) pk = other;
        }
        if (lane == 0) wmax[w] = pk;
        __syncthreads();
        if (o == 0) {
            unsigned long long best = wmax[0];
#pragma unroll
            for (int i = 1; i < 16; i++) if (wmax[i] > best) best = wmax[i];
            s_win = (K2 - 1) - (int)(unsigned)(best & 0xffffffffULL);
        }
        __syncthreads();
        if (o == s_win) {
            if (tot != 0.0f) sel = true;
            tot = 0.0f;
        }
        __syncthreads();
    }

#pragma unroll
    for (int t = 0; t < T_DIM; t++) {
        outp[t * K2 + o] = (sel && ((mask >> t) & 1u)) ? 1.0f : 0.0f;
    }
}

// ---------------------------------------------------------------------------
extern "C" void kernel_launch(void* const* d_in, const int* in_sizes, int n_in,
                              void* d_out, int out_size)
{
    const float* rec = (const float*)d_in[0];   // (32,1,64,4096)
    const float* wgt = (const float*)d_in[1];   // (512,1,64,4096)
    if (n_in >= 2 && in_sizes[0] > in_sizes[1]) {
        const float* tmp = rec; rec = wgt; wgt = tmp;
    }
    float* outp = (float*)d_out;

    cudaFuncSetAttribute(gemm_pipe, cudaFuncAttributeMaxDynamicSharedMemorySize,
                         SMEM_TOTAL);

    gemm_pipe<<<dim3(4, KSPLIT), 256, SMEM_TOTAL>>>(rec, wgt);
    reduce_kernel<<<dim3(T_DIM, 4), 128>>>();
    post_kernel<<<1, K2>>>(outp);
}

// round 16
// speedup vs baseline: 1.5597x; 1.1244x over previous
#include <cuda_runtime.h>
#include <cuda_bf16.h>
#include <cstdint>
#include <cstddef>

#define T_DIM  32
#define K2     512
#define KD     262144
#define THRESH 0.2f

#define KSPLIT 148                         // grid 4*148 = 592 = 148 SMs * 4
#define KSLAB  32                          // fp32 k per pipeline stage
#define NSLAB_TOT (KD / KSLAB)             // 8192
#define SBASE (NSLAB_TOT / KSPLIT)         // 55
#define SREM  (NSLAB_TOT - SBASE * KSPLIT) // 52

#define STAGES   2
#define A_STRIDE 160                       // 128B data + 32B pad: conflict-free lds64
#define A_BYTES  (128 * A_STRIDE)          // 20480
#define BH_OFF   A_BYTES
#define BB_STRIDE 80                       // bf16 rows: 64B data + 16B pad
#define BL_OFF   (BH_OFF + 32 * BB_STRIDE)
#define STAGE_BYTES (BL_OFF + 32 * BB_STRIDE)   // 25600
#define SMEM_TOTAL  (STAGES * STAGE_BYTES)      // 51200 (x4 CTAs = 204.8KB)

__device__ float g_partial[(size_t)KSPLIT * T_DIM * K2];
__device__ float g_dot[T_DIM * K2];

// ---------------- helpers ----------------
__device__ __forceinline__ uint32_t smem_u32(const void* p) {
    uint32_t a;
    asm("{ .reg .u64 t; cvta.to.shared.u64 t, %1; cvt.u32.u64 %0, t; }"
        : "=r"(a) : "l"(p));
    return a;
}
__device__ __forceinline__ void cp16(uint32_t dst, const void* src) {
    asm volatile("cp.async.cg.shared.global [%0], [%1], 16;"
                 :: "r"(dst), "l"(src) : "memory");
}
__device__ __forceinline__ float2 lds64(uint32_t a) {
    float2 v;
    asm volatile("ld.shared.v2.f32 {%0,%1}, [%2];"
                 : "=f"(v.x), "=f"(v.y) : "r"(a));
    return v;
}
__device__ __forceinline__ void sts64(uint32_t a, uint32_t x, uint32_t y) {
    asm volatile("st.shared.v2.b32 [%0], {%1,%2};" :: "r"(a), "r"(x), "r"(y)
                 : "memory");
}
__device__ __forceinline__ void ldsm_x4(uint32_t* r, uint32_t addr) {
    asm volatile("ldmatrix.sync.aligned.m8n8.x4.shared.b16 {%0,%1,%2,%3}, [%4];"
                 : "=r"(r[0]), "=r"(r[1]), "=r"(r[2]), "=r"(r[3]) : "r"(addr));
}
__device__ __forceinline__ void mma_bf16(float* c, const uint32_t* a, const uint32_t* b) {
    asm volatile("mma.sync.aligned.m16n8k16.row.col.f32.bf16.bf16.f32 "
                 "{%0,%1,%2,%3}, {%4,%5,%6,%7}, {%8,%9}, {%0,%1,%2,%3};"
                 : "+f"(c[0]), "+f"(c[1]), "+f"(c[2]), "+f"(c[3])
                 : "r"(a[0]), "r"(a[1]), "r"(a[2]), "r"(a[3]),
                   "r"(b[0]), "r"(b[1]));
}
__device__ __forceinline__ void cvt2(float a, float b, uint32_t& h, uint32_t& l) {
    __nv_bfloat162 hb = __floats2bfloat162_rn(a, b);
    float2 hf = __bfloat1622float2(hb);
    __nv_bfloat162 lb = __floats2bfloat162_rn(a - hf.x, b - hf.y);
    h = *reinterpret_cast<uint32_t*>(&hb);
    l = *reinterpret_cast<uint32_t*>(&lb);
}

// ---------------------------------------------------------------------------
// cp.async-pipelined HMMA GEMM, 2-stage ring, 4 CTAs/SM, 1 barrier/slab.
// A (W) staged fp32 via cp.async (conflict-free 160B rows);
// B (rec) LDG->reg->block convert->bf16 smem; ldmatrix.x4 B fragments.
// bf16 3-product (hh+hl+lh), fp32 accum. warp = 16 o x 32 t.
// (Exact R13 configuration — best measured.)
// ---------------------------------------------------------------------------
__global__ void __launch_bounds__(256, 4)
gemm_pipe(const float* __restrict__ rec, const float* __restrict__ wgt)
{
    extern __shared__ __align__(128) char smem[];
    const uint32_t sbase = smem_u32(smem);

    const int tid = threadIdx.x;
    const int wid = tid >> 5;
    const int lid = tid & 31;
    const int g   = lid >> 2;
    const int tig = lid & 3;
    const int ot  = blockIdx.x;        // 0..3
    const int sp  = blockIdx.y;        // 0..147
    const int obase = ot * 128;

    const int s_begin = sp * SBASE + (sp < SREM ? sp : SREM);
    const int s_count = SBASE + (sp < SREM ? 1 : 0);

    // ---- A staging map: thread covers rows (tid>>3)+32j, chunk tid&7 ----
    const float* asrc0 = wgt + (size_t)(obase + (tid >> 3)) * KD
                         + (size_t)s_begin * KSLAB + (tid & 7) * 4;
    const uint32_t adst0 = sbase + (uint32_t)((tid >> 3) * A_STRIDE + (tid & 7) * 16);

#define ISSUE(S)                                                              \
    {   const uint32_t so = (uint32_t)((S) & 1) * STAGE_BYTES;                 \
        const size_t ko = (size_t)(S) * KSLAB;                                 \
        cp16(adst0 + so,                    asrc0 + ko);                       \
        cp16(adst0 + so + 32 * A_STRIDE,    asrc0 + ko + (size_t)32 * KD);     \
        cp16(adst0 + so + 64 * A_STRIDE,    asrc0 + ko + (size_t)64 * KD);     \
        cp16(adst0 + so + 96 * A_STRIDE,    asrc0 + ko + (size_t)96 * KD); }

    // ---- B map: thread covers row tid>>3, chunk tid&7 (4 floats) ----
    const int brow = tid >> 3, bchk = tid & 7;
    const float* bsrc = rec + (size_t)brow * KD
                        + (size_t)s_begin * KSLAB + bchk * 4;
    const uint32_t cvt_h = sbase + (uint32_t)(BH_OFF + brow * BB_STRIDE + bchk * 8);
    const uint32_t cvt_l = sbase + (uint32_t)(BL_OFF + brow * BB_STRIDE + bchk * 8);

    // ---- compute lane addresses ----
    const uint32_t a0b = sbase + (uint32_t)((wid * 16 + g) * A_STRIDE + tig * 8);
    const uint32_t a1b = a0b + 8 * A_STRIDE;
    // ldsm x4 B address: lanes 0-15 -> n-tile nt, lanes 16-31 -> nt+1
    const uint32_t bb  = sbase + (uint32_t)(BH_OFF + (lid & 7) * BB_STRIDE
                          + ((lid >> 3) & 1) * 16
                          + (lid >> 4) * (8 * BB_STRIDE));

    float acc[4][4];
#pragma unroll
    for (int nt = 0; nt < 4; nt++)
#pragma unroll
        for (int i = 0; i < 4; i++) acc[nt][i] = 0.0f;

    // prologue
    ISSUE(0) asm volatile("cp.async.commit_group;" ::: "memory");
    float4 breg = *reinterpret_cast<const float4*>(bsrc);

    for (int s = 0; s < s_count; s++) {
        asm volatile("cp.async.wait_group 0;" ::: "memory");

        const uint32_t so = (uint32_t)(s & 1) * STAGE_BYTES;

        // block-shared B convert from registers into bf16 hi/lo tiles
        {
            uint32_t h0, l0, h1, l1;
            cvt2(breg.x, breg.y, h0, l0);
            cvt2(breg.z, breg.w, h1, l1);
            sts64(cvt_h + so, h0, h1);
            sts64(cvt_l + so, l0, l1);
        }
        __syncthreads();   // publishes A(s) + converted B(s); frees slot s^1

        if (s + 1 < s_count) {
            ISSUE(s + 1)
            breg = *reinterpret_cast<const float4*>(bsrc + (size_t)(s + 1) * KSLAB);
        }
        asm volatile("cp.async.commit_group;" ::: "memory");

#pragma unroll
        for (int ks = 0; ks < 2; ks++) {
            const uint32_t ao = so + ks * 64;
            const float2 f0 = lds64(a0b + ao);
            const float2 f1 = lds64(a1b + ao);
            const float2 f2 = lds64(a0b + ao + 32);
            const float2 f3 = lds64(a1b + ao + 32);
            uint32_t Ah[4], Al[4];
            cvt2(f0.x, f0.y, Ah[0], Al[0]);
            cvt2(f1.x, f1.y, Ah[1], Al[1]);
            cvt2(f2.x, f2.y, Ah[2], Al[2]);
            cvt2(f3.x, f3.y, Ah[3], Al[3]);
            const uint32_t bo = bb + so + ks * 32;
#pragma unroll
            for (int np = 0; np < 2; np++) {
                uint32_t Bh[4], Bl[4];          // two n-tiles per ldsm.x4
                ldsm_x4(Bh, bo + np * (16 * BB_STRIDE));
                ldsm_x4(Bl, bo + np * (16 * BB_STRIDE) + (BL_OFF - BH_OFF));
                mma_bf16(acc[np * 2 + 0], Ah, Bh + 0);
                mma_bf16(acc[np * 2 + 0], Ah, Bl + 0);
                mma_bf16(acc[np * 2 + 0], Al, Bh + 0);
                mma_bf16(acc[np * 2 + 1], Ah, Bh + 2);
                mma_bf16(acc[np * 2 + 1], Ah, Bl + 2);
                mma_bf16(acc[np * 2 + 1], Al, Bh + 2);
            }
        }
    }

    // epilogue
    const int orow = obase + wid * 16 + g;
#pragma unroll
    for (int nt = 0; nt < 4; nt++)
#pragma unroll
        for (int c = 0; c < 4; c++) {
            const int o = orow + ((c >> 1) ? 8 : 0);
            const int t = nt * 8 + 2 * tig + (c & 1);
            g_partial[((size_t)sp * T_DIM + t) * K2 + o] = acc[nt][c];
        }
}

// ---------------------------------------------------------------------------
// deterministic split-K reduction, 128 blocks (t x 4 o-chunks)
// ---------------------------------------------------------------------------
__global__ void __launch_bounds__(128) reduce_kernel()
{
    const int t = blockIdx.x;                      // 0..31
    const int o = blockIdx.y * 128 + threadIdx.x;  // 0..511
    const size_t stride = (size_t)T_DIM * K2;
    const size_t idx = (size_t)t * K2 + o;
    float s = 0.0f;
#pragma unroll
    for (int sp = 0; sp < KSPLIT; sp++)
        s += g_partial[(size_t)sp * stride + idx];
    g_dot[t * K2 + o] = s;
}

// ---------------------------------------------------------------------------
// post: threshold -> first-spike -> totals -> 8-round k-WTA (shuffle argmax)
// ---------------------------------------------------------------------------
__global__ void __launch_bounds__(512) post_kernel(float* __restrict__ outp)
{
    const int o    = threadIdx.x;
    const int lane = o & 31;
    const int w    = o >> 5;

    unsigned mask = 0;
    int cnt = 0;
#pragma unroll
    for (int t = 0; t < T_DIM; t++) {
        const float v = g_dot[t * K2 + o];
        if (v >= THRESH) { cnt++; mask |= (1u << t); }
    }
    int first = T_DIM - cnt;
    if (first > T_DIM - 1) first = T_DIM - 1;
    const float fv    = g_dot[first * K2 + o];
    const float value = (fv < THRESH) ? 0.0f : fv;
    const float cand  = (cnt > 0) ? value : 0.0f;

    __shared__ float wmaxf[16];
    __shared__ unsigned long long wmax[16];
    __shared__ int s_win;

    float m = cand;
#pragma unroll
    for (int off = 16; off; off >>= 1)
        m = fmaxf(m, __shfl_xor_sync(0xffffffffu, m, off));
    if (lane == 0) wmaxf[w] = m;
    __syncthreads();
    if (o == 0) {
        float mm = wmaxf[0];
#pragma unroll
        for (int i = 1; i < 16; i++) mm = fmaxf(mm, wmaxf[i]);
        wmaxf[0] = mm;
    }
    __syncthreads();
    const float voff = wmaxf[0] * (float)T_DIM;

    float tot = (cnt > 0) ? (float)cnt * (value + voff) : 0.0f;
    bool sel = false;

    for (int r = 0; r < 8; r++) {
        unsigned long long pk =
            ((unsigned long long)__float_as_uint(tot) << 32)
            | (unsigned)(K2 - 1 - o);
#pragma unroll
        for (int off = 16; off; off >>= 1) {
            unsigned long long other = __shfl_xor_sync(0xffffffffu, pk, off);
            if (other > pk) pk = other;
        }
        if (lane == 0) wmax[w] = pk;
        __syncthreads();
        if (o == 0) {
            unsigned long long best = wmax[0];
#pragma unroll
            for (int i = 1; i < 16; i++) if (wmax[i] > best) best = wmax[i];
            s_win = (K2 - 1) - (int)(unsigned)(best & 0xffffffffULL);
        }
        __syncthreads();
        if (o == s_win) {
            if (tot != 0.0f) sel = true;
            tot = 0.0f;
        }
        __syncthreads();
    }

#pragma unroll
    for (int t = 0; t < T_DIM; t++) {
        outp[t * K2 + o] = (sel && ((mask >> t) & 1u)) ? 1.0f : 0.0f;
    }
}

// ---------------------------------------------------------------------------
extern "C" void kernel_launch(void* const* d_in, const int* in_sizes, int n_in,
                              void* d_out, int out_size)
{
    const float* rec = (const float*)d_in[0];   // (32,1,64,4096)
    const float* wgt = (const float*)d_in[1];   // (512,1,64,4096)
    if (n_in >= 2 && in_sizes[0] > in_sizes[1]) {
        const float* tmp = rec; rec = wgt; wgt = tmp;
    }
    float* outp = (float*)d_out;

    cudaFuncSetAttribute(gemm_pipe, cudaFuncAttributeMaxDynamicSharedMemorySize,
                         SMEM_TOTAL);

    gemm_pipe<<<dim3(4, KSPLIT), 256, SMEM_TOTAL>>>(rec, wgt);
    reduce_kernel<<<dim3(T_DIM, 4), 128>>>();
    post_kernel<<<1, K2>>>(outp);
}